// round 14
// baseline (speedup 1.0000x reference)
#include <cuda_runtime.h>
#include <cstdio>
#include <cstdlib>
#include <math.h>

#define BB 2
#define TT 4096
#define CC 1024
#define HH 16
#define DD 64
#define MM (BB*TT)   // 8192

// ---------------- scratch -----------------------------------------------------
__device__ float g_xt[(size_t)MM * CC];   // tf32-rounded x
__device__ float g_wt[4][(size_t)CC * CC];// tf32-rounded Wq,Wk,Wv,Wo (contiguous)
__device__ float g_q2[(size_t)MM * CC];   // roped q  [B,T,C]
__device__ float g_k2[(size_t)MM * CC];   // roped k
__device__ float g_v [(size_t)MM * CC];
__device__ float g_o [(size_t)MM * CC];   // attention out (tf32-rounded)

__constant__ float c_inv[32] = {
    1.0f,            0.749894209f,   0.562341325f,   0.421696503f,
    0.316227766f,    0.237137371f,   0.177827941f,   0.133352143f,
    0.1f,            0.0749894209f,  0.0562341325f,  0.0421696503f,
    0.0316227766f,   0.0237137371f,  0.0177827941f,  0.0133352143f,
    0.01f,           0.00749894209f, 0.00562341325f, 0.00421696503f,
    0.00316227766f,  0.00237137371f, 0.00177827941f, 0.00133352143f,
    0.001f,          0.000749894209f,0.000562341325f,0.000421696503f,
    0.000316227766f, 0.000237137371f,0.000177827941f,0.000133352143f
};
static const float h_inv[32] = {
    1.0f,            0.749894209f,   0.562341325f,   0.421696503f,
    0.316227766f,    0.237137371f,   0.177827941f,   0.133352143f,
    0.1f,            0.0749894209f,  0.0562341325f,  0.0421696503f,
    0.0316227766f,   0.0237137371f,  0.0177827941f,  0.0133352143f,
    0.01f,           0.00749894209f, 0.00562341325f, 0.00421696503f,
    0.00316227766f,  0.00237137371f, 0.00177827941f, 0.00133352143f,
    0.001f,          0.000749894209f,0.000562341325f,0.000421696503f,
    0.000316227766f, 0.000237137371f,0.000177827941f,0.000133352143f
};

__device__ __forceinline__ void safe_sincos(float ang, float* c, float* s)
{
    float k = rintf(ang * 0.159154943091895f);
    float r = fmaf(-k, 6.28318530717958f, ang);
    r = fmaf(-k, -1.7484556e-07f, r);
    sincosf(r, s, c);                     // CUDA: sin first, cos second!
}

__device__ __forceinline__ unsigned f2tf32(float x)
{
    unsigned r;
    asm("cvt.rna.tf32.f32 %0, %1;" : "=r"(r) : "f"(x));
    return r;
}

// FMA-only 2^y for y <= 0; no MUFU.
__device__ __forceinline__ float fexp2(float y)
{
    y = fmaxf(y, -100.0f);
    float z = y + 12582912.0f;
    int   i = __float_as_int(z) - 0x4B400000;
    float f = y - (z - 12582912.0f);
    float p =           0.0013333558f;
    p = fmaf(p, f, 0.0096181291f);
    p = fmaf(p, f, 0.0555041087f);
    p = fmaf(p, f, 0.2402265069f);
    p = fmaf(p, f, 0.6931471806f);
    p = fmaf(p, f, 1.0f);
    return __int_as_float(__float_as_int(p) + (i << 23));
}

#define MMA_TF32(acc, a0, a1, a2, a3, b0, b1)                                  \
    asm volatile(                                                              \
        "mma.sync.aligned.m16n8k8.row.col.f32.tf32.tf32.f32 "                  \
        "{%0,%1,%2,%3}, {%4,%5,%6,%7}, {%8,%9}, {%0,%1,%2,%3};"                \
        : "+f"(acc[0]), "+f"(acc[1]), "+f"(acc[2]), "+f"(acc[3])               \
        : "r"(a0), "r"(a1), "r"(a2), "r"(a3), "r"(b0), "r"(b1))

__device__ __forceinline__ void cpa16(unsigned saddr, const void* gptr)
{
    asm volatile("cp.async.ca.shared.global [%0], [%1], 16;"
                 :: "r"(saddr), "l"(gptr) : "memory");
}
#define CP_COMMIT() asm volatile("cp.async.commit_group;" ::: "memory")
#define CP_WAIT(N)  asm volatile("cp.async.wait_group %0;" :: "n"(N) : "memory")

// ---------------- tf32 pre-rounding pass -------------------------------------
__global__ void cvt_tf32(const float* __restrict__ in, float* __restrict__ out)
{
    size_t i = ((size_t)blockIdx.x * blockDim.x + threadIdx.x) * 4;
    float4 v = *(const float4*)&in[i];
    uint4 r = make_uint4(f2tf32(v.x), f2tf32(v.y), f2tf32(v.z), f2tf32(v.w));
    *(uint4*)&out[i] = r;
}

// ---------------- GEMM core (shared by qkv and out paths) --------------------
#define GBM 128
#define GBN 128
#define BK2 32
#define STG_F (128 * BK2)
#define SW(m, k) ((m) * BK2 + (((k) ^ (((m) & 7) << 2)) & 31))
#define GEMM_SMEM (4 * STG_F * 4)          // 64KB

// computes 128x128 tile: acc = A[m0..][*] . W[n0..][*]^T ; A,W tf32-pre-rounded
__device__ __forceinline__ void gemm_tile(
    const float* __restrict__ A, const float* __restrict__ W,
    int m0, int n0, float c[2][8][4], float* As, float* Bs,
    unsigned sA, unsigned sB, int tid, int wm, int wn, int lq, int lr)
{
#define STAGE_LOAD(stg, kbase)                                                 \
    do {                                                                       \
        _Pragma("unroll")                                                      \
        for (int it = 0; it < 4; it++) {                                       \
            int lin = tid + it * 256;                                          \
            int row = lin >> 3;                                                \
            int kk  = (lin & 7) << 2;                                          \
            cpa16(sA + ((stg) * STG_F + SW(row, kk)) * 4,                      \
                  &A[(size_t)(m0 + row) * CC + (kbase) + kk]);                 \
            cpa16(sB + ((stg) * STG_F + SW(row, kk)) * 4,                      \
                  &W[(size_t)(n0 + row) * CC + (kbase) + kk]);                 \
        }                                                                      \
    } while (0)

    STAGE_LOAD(0, 0);
    CP_COMMIT();

    int buf = 0;
    for (int k0 = 0; k0 < CC; k0 += BK2) {
        if (k0 + BK2 < CC) {
            STAGE_LOAD(buf ^ 1, k0 + BK2);
            CP_COMMIT();
            CP_WAIT(1);
        } else {
            CP_WAIT(0);
        }
        __syncthreads();

        const float* Ab = As + buf * STG_F;
        const float* Bb = Bs + buf * STG_F;
#pragma unroll
        for (int ks = 0; ks < BK2; ks += 8) {
            unsigned af[2][4];
#pragma unroll
            for (int mi = 0; mi < 2; mi++) {
                int rlo = wm + mi * 16 + lq;
                af[mi][0] = __float_as_uint(Ab[SW(rlo,     ks + lr)]);
                af[mi][1] = __float_as_uint(Ab[SW(rlo + 8, ks + lr)]);
                af[mi][2] = __float_as_uint(Ab[SW(rlo,     ks + 4 + lr)]);
                af[mi][3] = __float_as_uint(Ab[SW(rlo + 8, ks + 4 + lr)]);
            }
            unsigned bf[8][2];
#pragma unroll
            for (int ni = 0; ni < 8; ni++) {
                int col = wn + ni * 8 + lq;
                bf[ni][0] = __float_as_uint(Bb[SW(col, ks + lr)]);
                bf[ni][1] = __float_as_uint(Bb[SW(col, ks + 4 + lr)]);
            }
#pragma unroll
            for (int mi = 0; mi < 2; mi++)
#pragma unroll
                for (int ni = 0; ni < 8; ni++)
                    MMA_TF32(c[mi][ni], af[mi][0], af[mi][1], af[mi][2], af[mi][3],
                             bf[ni][0], bf[ni][1]);
        }
        __syncthreads();
        buf ^= 1;
    }
#undef STAGE_LOAD
}

__device__ __forceinline__ void rope_regs(float c[2][8][4], int m0, int wm, int lq, int lr)
{
#pragma unroll
    for (int mi = 0; mi < 2; mi++) {
        int rbase = m0 + wm + mi * 16 + lq;
#pragma unroll
        for (int rr = 0; rr < 2; rr++) {
            int t = (rbase + 8 * rr) & (TT - 1);
#pragma unroll
            for (int ni = 0; ni < 4; ni++) {
#pragma unroll
                for (int c2 = 0; c2 < 2; c2++) {
                    int j = ni * 8 + 2 * lr + c2;
                    float cs, sn;
                    safe_sincos((float)t * c_inv[j], &cs, &sn);
                    int idx = 2 * rr + c2;
                    float a1 = c[mi][ni][idx], a2 = c[mi][ni + 4][idx];
                    c[mi][ni][idx]     = a1 * cs - a2 * sn;
                    c[mi][ni + 4][idx] = a2 * cs + a1 * sn;
                }
            }
        }
    }
}

__device__ __forceinline__ void store_tile(float* __restrict__ Cout, int m0, int n0,
                                           float c[2][8][4], int wm, int wn, int lq, int lr)
{
#pragma unroll
    for (int mi = 0; mi < 2; mi++) {
        int rlo = m0 + wm + mi * 16 + lq;
#pragma unroll
        for (int ni = 0; ni < 8; ni++) {
            int cc = n0 + wn + ni * 8 + 2 * lr;
            *(float2*)&Cout[(size_t)rlo * CC + cc] =
                make_float2(c[mi][ni][0], c[mi][ni][1]);
            *(float2*)&Cout[(size_t)(rlo + 8) * CC + cc] =
                make_float2(c[mi][ni][2], c[mi][ni][3]);
        }
    }
}

// ---- fused QKV GEMM: W = concatenated [3072 x 1024]; routes per n-block -----
__global__ __launch_bounds__(256)
void qkv_gemm(const float* __restrict__ A, const float* __restrict__ Wqkv)
{
    extern __shared__ float gsm[];
    float* As = gsm;
    float* Bs = gsm + 2 * STG_F;

    const int tid  = threadIdx.x;
    const int lane = tid & 31;
    const int w    = tid >> 5;
    const int wm   = (w >> 1) * 32;
    const int wn   = (w & 1) * 64;
    const int m0 = blockIdx.y * GBM;
    const int ng = blockIdx.x * GBN;          // 0..2944, global n in [0,3072)
    const int lq = lane >> 2;
    const int lr = lane & 3;

    const unsigned sA = (unsigned)__cvta_generic_to_shared(As);
    const unsigned sB = (unsigned)__cvta_generic_to_shared(Bs);

    float c[2][8][4];
#pragma unroll
    for (int mi = 0; mi < 2; mi++)
#pragma unroll
        for (int ni = 0; ni < 8; ni++)
#pragma unroll
            for (int r = 0; r < 4; r++) c[mi][ni][r] = 0.f;

    gemm_tile(A, Wqkv, m0, ng, c, As, Bs, sA, sB, tid, wm, wn, lq, lr);

    float* out = (ng < 1024) ? g_q2 : (ng < 2048) ? g_k2 : g_v;
    if (ng < 2048) rope_regs(c, m0, wm, lq, lr);
    store_tile(out, m0, ng & 1023, c, wm, wn, lq, lr);
}

// ---- plain GEMM (output projection) -----------------------------------------
__global__ __launch_bounds__(256)
void pgemm(const float* __restrict__ A, const float* __restrict__ W,
           float* __restrict__ Cout)
{
    extern __shared__ float gsm[];
    float* As = gsm;
    float* Bs = gsm + 2 * STG_F;

    const int tid  = threadIdx.x;
    const int lane = tid & 31;
    const int w    = tid >> 5;
    const int wm   = (w >> 1) * 32;
    const int wn   = (w & 1) * 64;
    const int m0 = blockIdx.y * GBM;
    const int n0 = blockIdx.x * GBN;
    const int lq = lane >> 2;
    const int lr = lane & 3;

    const unsigned sA = (unsigned)__cvta_generic_to_shared(As);
    const unsigned sB = (unsigned)__cvta_generic_to_shared(Bs);

    float c[2][8][4];
#pragma unroll
    for (int mi = 0; mi < 2; mi++)
#pragma unroll
        for (int ni = 0; ni < 8; ni++)
#pragma unroll
            for (int r = 0; r < 4; r++) c[mi][ni][r] = 0.f;

    gemm_tile(A, W, m0, n0, c, As, Bs, sA, sB, tid, wm, wn, lq, lr);
    store_tile(Cout, m0, n0, c, wm, wn, lq, lr);
}

// ---------------- tensor-core flash attention (verified R11-R13) -------------
#define QLD 68
#define VLD 72
#define FLASH_SMEM ((3 * 64 * QLD + 64 * VLD) * 4)   // 70656 B

__global__ __launch_bounds__(128)
void flash_tc()
{
    extern __shared__ unsigned fsm[];
    unsigned* Qs = fsm;
    unsigned* Ks = fsm + 64 * QLD;
    unsigned* Ps = fsm + 2 * 64 * QLD;
    unsigned* Vs = fsm + 3 * 64 * QLD;

    const int tid  = threadIdx.x;
    const int lane = tid & 31;
    const int strip = (tid >> 5) * 16;
    const int lq = lane >> 2, lr = lane & 3;

    const int bh = blockIdx.y;
    const int b = bh >> 4, h = bh & 15;
    const int qb = gridDim.x - 1 - blockIdx.x;
    const int t0q = qb * 64;
    const size_t base = (size_t)b * TT * CC + h * DD;

    const float qsc = 0.125f * 1.44269504f;
#pragma unroll
    for (int it = 0; it < 8; it++) {
        int lin = tid + it * 128;
        int row = lin >> 4, c4 = (lin & 15) << 2;
        float4 a = *(const float4*)&g_q2[base + (size_t)(t0q + row) * CC + c4];
        *(uint4*)&Qs[row * QLD + c4] =
            make_uint4(f2tf32(a.x * qsc), f2tf32(a.y * qsc),
                       f2tf32(a.z * qsc), f2tf32(a.w * qsc));
    }

    float m_i[2] = {-INFINITY, -INFINITY};
    float l_i[2] = {0.f, 0.f};
    float oa[8][4];
#pragma unroll
    for (int ni = 0; ni < 8; ni++)
#pragma unroll
        for (int r = 0; r < 4; r++) oa[ni][r] = 0.f;

    for (int jt = 0; jt <= qb; jt++) {
        __syncthreads();
        const int t0k = jt * 64;
#pragma unroll
        for (int it = 0; it < 8; it++) {
            int lin = tid + it * 128;
            int row = lin >> 4, c4 = (lin & 15) << 2;
            float4 kv = *(const float4*)&g_k2[base + (size_t)(t0k + row) * CC + c4];
            *(uint4*)&Ks[row * QLD + c4] =
                make_uint4(f2tf32(kv.x), f2tf32(kv.y), f2tf32(kv.z), f2tf32(kv.w));
            float4 vv = *(const float4*)&g_v[base + (size_t)(t0k + row) * CC + c4];
            *(uint4*)&Vs[row * VLD + c4] =
                make_uint4(f2tf32(vv.x), f2tf32(vv.y), f2tf32(vv.z), f2tf32(vv.w));
        }
        __syncthreads();

        float sa[8][4];
#pragma unroll
        for (int ni = 0; ni < 8; ni++)
#pragma unroll
            for (int r = 0; r < 4; r++) sa[ni][r] = 0.f;

#pragma unroll
        for (int ks = 0; ks < 64; ks += 8) {
            unsigned a0 = Qs[(strip + lq) * QLD + ks + lr];
            unsigned a1 = Qs[(strip + lq + 8) * QLD + ks + lr];
            unsigned a2 = Qs[(strip + lq) * QLD + ks + 4 + lr];
            unsigned a3 = Qs[(strip + lq + 8) * QLD + ks + 4 + lr];
#pragma unroll
            for (int ni = 0; ni < 8; ni++) {
                unsigned b0 = Ks[(ni * 8 + lq) * QLD + ks + lr];
                unsigned b1 = Ks[(ni * 8 + lq) * QLD + ks + 4 + lr];
                MMA_TF32(sa[ni], a0, a1, a2, a3, b0, b1);
            }
        }

        if (jt == qb) {
            int r0 = strip + lq, r1 = r0 + 8;
#pragma unroll
            for (int ni = 0; ni < 8; ni++) {
                int col = ni * 8 + 2 * lr;
                if (col     > r0) sa[ni][0] = -1e30f;
                if (col + 1 > r0) sa[ni][1] = -1e30f;
                if (col     > r1) sa[ni][2] = -1e30f;
                if (col + 1 > r1) sa[ni][3] = -1e30f;
            }
        }

#pragma unroll
        for (int r = 0; r < 2; r++) {
            float mx = fmaxf(sa[0][2 * r], sa[0][2 * r + 1]);
#pragma unroll
            for (int ni = 1; ni < 8; ni++)
                mx = fmaxf(mx, fmaxf(sa[ni][2 * r], sa[ni][2 * r + 1]));
            mx = fmaxf(mx, __shfl_xor_sync(0xffffffffu, mx, 1));
            mx = fmaxf(mx, __shfl_xor_sync(0xffffffffu, mx, 2));
            float mnew  = fmaxf(m_i[r], mx);
            float alpha = fexp2(m_i[r] - mnew);
            m_i[r] = mnew;
            float sum = 0.f;
            int prow = (strip + lq + 8 * r) * QLD;
#pragma unroll
            for (int ni = 0; ni < 8; ni++) {
                float p0 = fexp2(sa[ni][2 * r] - mnew);
                float p1 = fexp2(sa[ni][2 * r + 1] - mnew);
                sum += p0 + p1;
                Ps[prow + ni * 8 + 2 * lr]     = f2tf32(p0);
                Ps[prow + ni * 8 + 2 * lr + 1] = f2tf32(p1);
            }
            sum += __shfl_xor_sync(0xffffffffu, sum, 1);
            sum += __shfl_xor_sync(0xffffffffu, sum, 2);
            l_i[r] = l_i[r] * alpha + sum;
#pragma unroll
            for (int ni = 0; ni < 8; ni++) {
                oa[ni][2 * r]     *= alpha;
                oa[ni][2 * r + 1] *= alpha;
            }
        }
        __syncwarp();

#pragma unroll
        for (int ks = 0; ks < 64; ks += 8) {
            unsigned a0 = Ps[(strip + lq) * QLD + ks + lr];
            unsigned a1 = Ps[(strip + lq + 8) * QLD + ks + lr];
            unsigned a2 = Ps[(strip + lq) * QLD + ks + 4 + lr];
            unsigned a3 = Ps[(strip + lq + 8) * QLD + ks + 4 + lr];
#pragma unroll
            for (int ni = 0; ni < 8; ni++) {
                unsigned b0 = Vs[(ks + lr) * VLD + ni * 8 + lq];
                unsigned b1 = Vs[(ks + 4 + lr) * VLD + ni * 8 + lq];
                MMA_TF32(oa[ni], a0, a1, a2, a3, b0, b1);
            }
        }
    }

    float inv0 = 1.f / l_i[0], inv1 = 1.f / l_i[1];
    int t0 = t0q + strip + lq;
#pragma unroll
    for (int ni = 0; ni < 8; ni++) {
        int d = ni * 8 + 2 * lr;
        *(uint2*)&g_o[base + (size_t)t0 * CC + d] =
            make_uint2(f2tf32(oa[ni][0] * inv0), f2tf32(oa[ni][1] * inv0));
        *(uint2*)&g_o[base + (size_t)(t0 + 8) * CC + d] =
            make_uint2(f2tf32(oa[ni][2] * inv1), f2tf32(oa[ni][3] * inv1));
    }
}

// ---------------- launch -----------------------------------------------------
static float hA[1024], hB[1024], hC[1024], hD[1024], hV1[1024], ho1[1024];
static float hW[(size_t)CC * CC];
static float hx2[2 * CC];

extern "C" void kernel_launch(void* const* d_in, const int* in_sizes, int n_in,
                              void* d_out, int out_size)
{
    const float* x  = (const float*)d_in[0];
    const float* Wq = (const float*)d_in[1];
    const float* Wk = (const float*)d_in[2];
    const float* Wv = (const float*)d_in[3];
    const float* Wo = (const float*)d_in[4];

    float *xt, *wt, *op;
    cudaGetSymbolAddress((void**)&xt, g_xt);
    cudaGetSymbolAddress((void**)&wt, g_wt);
    cudaGetSymbolAddress((void**)&op, g_o);
    float* wt0 = wt;
    float* wt1 = wt + (size_t)CC * CC;
    float* wt2 = wt + 2 * (size_t)CC * CC;
    float* wt3 = wt + 3 * (size_t)CC * CC;

    static int smem_set = 0;
    if (!smem_set) {
        cudaFuncSetAttribute(flash_tc,
                             cudaFuncAttributeMaxDynamicSharedMemorySize,
                             FLASH_SMEM);
        cudaFuncSetAttribute(pgemm,
                             cudaFuncAttributeMaxDynamicSharedMemorySize,
                             GEMM_SMEM);
        cudaFuncSetAttribute(qkv_gemm,
                             cudaFuncAttributeMaxDynamicSharedMemorySize,
                             GEMM_SMEM);
        smem_set = 1;
    }

    // pre-round to tf32 (RNA) once
    cvt_tf32<<<(MM * CC) / 1024, 256>>>(x, xt);
    cvt_tf32<<<(CC * CC) / 1024, 256>>>(Wq, wt0);
    cvt_tf32<<<(CC * CC) / 1024, 256>>>(Wk, wt1);
    cvt_tf32<<<(CC * CC) / 1024, 256>>>(Wv, wt2);
    cvt_tf32<<<(CC * CC) / 1024, 256>>>(Wo, wt3);

    // fused QKV projection + rope (wt0..wt2 contiguous = [3072 x 1024])
    qkv_gemm<<<dim3(3 * CC / GBN, MM / GBM), 256, GEMM_SMEM>>>(xt, wt0);

    flash_tc<<<dim3(TT / 64, BB * HH), 128, FLASH_SMEM>>>();

    pgemm<<<dim3(CC / GBN, MM / GBM), 256, GEMM_SMEM>>>(op, wt3, (float*)d_out);

    // ---- capture-guarded host verification; rc=3 only on failure ------------
    cudaStreamCaptureStatus csx = cudaStreamCaptureStatusNone;
    cudaStreamIsCapturing(0, &csx);
    if (csx != cudaStreamCaptureStatusNone) return;

    cudaError_t e = cudaDeviceSynchronize();
    if (e != cudaSuccess) {
        printf("[HC] pipeline error: %s\n", cudaGetErrorString(e));
        fflush(stdout); exit(3);
    }
    int bad = 0;

    // (1)+(2) q2 rows 0 and 1 vs host x.Wq^T (+rotation at t=1)
    cudaMemcpy(hW, Wq, (size_t)CC * CC * 4, cudaMemcpyDeviceToHost);
    cudaMemcpy(hx2, x, 2 * CC * 4, cudaMemcpyDeviceToHost);
    cudaMemcpyFromSymbol(hA, g_q2, 1024 * 4, 0);
    cudaMemcpyFromSymbol(hB, g_q2, 1024 * 4, (size_t)CC * 4);
    {
        static double raw1[1024];
        for (int ch = 0; ch < 1024; ch++) {
            double e0 = 0, e1 = 0;
            for (int k = 0; k < 1024; k++) {
                e0 += (double)hx2[k] * hW[(size_t)ch * CC + k];
                e1 += (double)hx2[CC + k] * hW[(size_t)ch * CC + k];
            }
            raw1[ch] = e1;
            if (fabs(e0 - hA[ch]) > 4e-3 * (fabs(e0) + 1.0) && bad < 8) {
                printf("[HC] q2 t0 ch=%d got %.6g exp %.6g\n", ch, hA[ch], e0);
                bad++;
            }
        }
        for (int h = 0; h < HH && bad < 8; h++)
            for (int j = 0; j < 32 && bad < 8; j++) {
                int ch = h * DD + j;
                double cq = cos((double)h_inv[j]), sq = sin((double)h_inv[j]);
                double r1 = raw1[ch] * cq - raw1[ch + 32] * sq;
                double r2 = raw1[ch + 32] * cq + raw1[ch] * sq;
                if (fabs(r1 - hB[ch]) > 4e-3 * (fabs(r1) + 1.0) ||
                    fabs(r2 - hB[ch + 32]) > 4e-3 * (fabs(r2) + 1.0)) {
                    printf("[HC] q2 t1 h=%d j=%d got(%.6g,%.6g) exp(%.6g,%.6g)\n",
                           h, j, hB[ch], hB[ch + 32], r1, r2);
                    bad++;
                }
            }
    }
    // (3) attention t=0: o == v
    cudaMemcpyFromSymbol(hC, g_o, 1024 * 4, 0);
    cudaMemcpyFromSymbol(hD, g_v, 1024 * 4, 0);
    for (int ch = 0; ch < 1024 && bad < 8; ch++)
        if (fabsf(hC[ch] - hD[ch]) > 2e-3f * (fabsf(hD[ch]) + 1e-1f)) {
            printf("[HC] attn t0 ch=%d o=%.6g v=%.6g\n", ch, hC[ch], hD[ch]);
            bad++;
        }
    // (4) attention t=1: two-key softmax vs host
    {
        cudaMemcpyFromSymbol(hA, g_q2, 1024 * 4, (size_t)CC * 4);
        cudaMemcpyFromSymbol(hB, g_k2, 1024 * 4, 0);
        cudaMemcpyFromSymbol(hC, g_k2, 1024 * 4, (size_t)CC * 4);
        cudaMemcpyFromSymbol(hD, g_v,  1024 * 4, 0);
        cudaMemcpyFromSymbol(hV1, g_v, 1024 * 4, (size_t)CC * 4);
        cudaMemcpyFromSymbol(ho1, g_o, 1024 * 4, (size_t)CC * 4);
        for (int h = 0; h < HH && bad < 8; h++) {
            double s0 = 0, s1 = 0;
            for (int d = 0; d < DD; d++) {
                s0 += (double)hA[h * DD + d] * hB[h * DD + d];
                s1 += (double)hA[h * DD + d] * hC[h * DD + d];
            }
            s0 *= 0.125; s1 *= 0.125;
            double m = s0 > s1 ? s0 : s1;
            double p0 = exp(s0 - m), p1 = exp(s1 - m), Z = p0 + p1;
            for (int d = 0; d < DD && bad < 8; d++) {
                double oe = (p0 * hD[h * DD + d] + p1 * hV1[h * DD + d]) / Z;
                if (fabs(oe - ho1[h * DD + d]) > 3e-3) {
                    printf("[HC] attn t1 h=%d d=%d got %.6g exp %.6g\n",
                           h, d, ho1[h * DD + d], oe);
                    bad++;
                }
            }
        }
    }
    // (5) final out[0,0:4] vs host dot
    {
        cudaMemcpyFromSymbol(hC, g_o, 1024 * 4, 0);
        cudaMemcpy(hW, Wo, 4096 * 4, cudaMemcpyDeviceToHost);
        float hout[4];
        cudaMemcpy(hout, d_out, 16, cudaMemcpyDeviceToHost);
        for (int r = 0; r < 4; r++) {
            double ex = 0;
            for (int k = 0; k < 1024; k++) ex += (double)hC[k] * hW[r * 1024 + k];
            if (fabs(ex - hout[r]) > 2e-3 * (fabs(ex) + 1.0)) {
                printf("[HC] out0 r=%d got %.6g exp %.6g\n", r, hout[r], ex);
                bad++;
            }
        }
    }
    if (bad) { printf("[HC] FAILED %d checks\n", bad); fflush(stdout); exit(3); }
}

// round 15
// speedup vs baseline: 1.0499x; 1.0499x over previous
#include <cuda_runtime.h>
#include <cstdio>
#include <cstdlib>
#include <math.h>

#define BB 2
#define TT 4096
#define CC 1024
#define HH 16
#define DD 64
#define MM (BB*TT)   // 8192

// ---------------- scratch -----------------------------------------------------
__device__ float g_xt[(size_t)MM * CC];   // tf32-rounded x
__device__ float g_wt[4][(size_t)CC * CC];// tf32-rounded Wq,Wk,Wv,Wo
__device__ float g_q2[(size_t)MM * CC];   // roped q  [B,T,C]
__device__ float g_k2[(size_t)MM * CC];   // roped k
__device__ float g_v [(size_t)MM * CC];
__device__ float g_o [(size_t)MM * CC];   // attention out (tf32-rounded)

__constant__ float c_inv[32] = {
    1.0f,            0.749894209f,   0.562341325f,   0.421696503f,
    0.316227766f,    0.237137371f,   0.177827941f,   0.133352143f,
    0.1f,            0.0749894209f,  0.0562341325f,  0.0421696503f,
    0.0316227766f,   0.0237137371f,  0.0177827941f,  0.0133352143f,
    0.01f,           0.00749894209f, 0.00562341325f, 0.00421696503f,
    0.00316227766f,  0.00237137371f, 0.00177827941f, 0.00133352143f,
    0.001f,          0.000749894209f,0.000562341325f,0.000421696503f,
    0.000316227766f, 0.000237137371f,0.000177827941f,0.000133352143f
};
static const float h_inv[32] = {
    1.0f,            0.749894209f,   0.562341325f,   0.421696503f,
    0.316227766f,    0.237137371f,   0.177827941f,   0.133352143f,
    0.1f,            0.0749894209f,  0.0562341325f,  0.0421696503f,
    0.0316227766f,   0.0237137371f,  0.0177827941f,  0.0133352143f,
    0.01f,           0.00749894209f, 0.00562341325f, 0.00421696503f,
    0.00316227766f,  0.00237137371f, 0.00177827941f, 0.00133352143f,
    0.001f,          0.000749894209f,0.000562341325f,0.000421696503f,
    0.000316227766f, 0.000237137371f,0.000177827941f,0.000133352143f
};

__device__ __forceinline__ void safe_sincos(float ang, float* c, float* s)
{
    float k = rintf(ang * 0.159154943091895f);
    float r = fmaf(-k, 6.28318530717958f, ang);
    r = fmaf(-k, -1.7484556e-07f, r);
    sincosf(r, s, c);                     // CUDA: sin first, cos second!
}

__device__ __forceinline__ unsigned f2tf32(float x)
{
    unsigned r;
    asm("cvt.rna.tf32.f32 %0, %1;" : "=r"(r) : "f"(x));
    return r;
}

// FMA-only 2^y for y <= 0; no MUFU.
__device__ __forceinline__ float fexp2(float y)
{
    y = fmaxf(y, -100.0f);
    float z = y + 12582912.0f;
    int   i = __float_as_int(z) - 0x4B400000;
    float f = y - (z - 12582912.0f);
    float p =           0.0013333558f;
    p = fmaf(p, f, 0.0096181291f);
    p = fmaf(p, f, 0.0555041087f);
    p = fmaf(p, f, 0.2402265069f);
    p = fmaf(p, f, 0.6931471806f);
    p = fmaf(p, f, 1.0f);
    return __int_as_float(__float_as_int(p) + (i << 23));
}

#define MMA_TF32(acc, a0, a1, a2, a3, b0, b1)                                  \
    asm volatile(                                                              \
        "mma.sync.aligned.m16n8k8.row.col.f32.tf32.tf32.f32 "                  \
        "{%0,%1,%2,%3}, {%4,%5,%6,%7}, {%8,%9}, {%0,%1,%2,%3};"                \
        : "+f"(acc[0]), "+f"(acc[1]), "+f"(acc[2]), "+f"(acc[3])               \
        : "r"(a0), "r"(a1), "r"(a2), "r"(a3), "r"(b0), "r"(b1))

__device__ __forceinline__ void cpa16(unsigned saddr, const void* gptr)
{
    asm volatile("cp.async.ca.shared.global [%0], [%1], 16;"
                 :: "r"(saddr), "l"(gptr) : "memory");
}
#define CP_COMMIT() asm volatile("cp.async.commit_group;" ::: "memory")
#define CP_WAIT(N)  asm volatile("cp.async.wait_group %0;" :: "n"(N) : "memory")

// ---------------- tf32 pre-rounding pass -------------------------------------
__global__ void cvt_tf32(const float* __restrict__ in, float* __restrict__ out)
{
    size_t i = ((size_t)blockIdx.x * blockDim.x + threadIdx.x) * 4;
    float4 v = *(const float4*)&in[i];
    uint4 r = make_uint4(f2tf32(v.x), f2tf32(v.y), f2tf32(v.z), f2tf32(v.w));
    *(uint4*)&out[i] = r;
}

// ---------------- pipelined TF32 GEMM (R13, known-good) ----------------------
#define GBM 128
#define GBN 128
#define BK2 32
#define STG_F (128 * BK2)
#define SW(m, k) ((m) * BK2 + (((k) ^ (((m) & 7) << 2)) & 31))
#define GEMM_SMEM (4 * STG_F * 4)          // 64KB

__global__ __launch_bounds__(256)
void pgemm(const float* __restrict__ A, const float* __restrict__ W,
           float* __restrict__ Cout, int do_rope)
{
    extern __shared__ float gsm[];
    float* As = gsm;
    float* Bs = gsm + 2 * STG_F;

    const int tid  = threadIdx.x;
    const int lane = tid & 31;
    const int w    = tid >> 5;
    const int wm   = (w >> 1) * 32;
    const int wn   = (w & 1) * 64;
    const int m0 = blockIdx.y * GBM;
    const int n0 = blockIdx.x * GBN;
    const int lq = lane >> 2;
    const int lr = lane & 3;

    const unsigned sA = (unsigned)__cvta_generic_to_shared(As);
    const unsigned sB = (unsigned)__cvta_generic_to_shared(Bs);

    float c[2][8][4];
#pragma unroll
    for (int mi = 0; mi < 2; mi++)
#pragma unroll
        for (int ni = 0; ni < 8; ni++)
#pragma unroll
            for (int r = 0; r < 4; r++) c[mi][ni][r] = 0.f;

#define STAGE_LOAD(stg, kbase)                                                 \
    do {                                                                       \
        _Pragma("unroll")                                                      \
        for (int it = 0; it < 4; it++) {                                       \
            int lin = tid + it * 256;                                          \
            int row = lin >> 3;                                                \
            int kk  = (lin & 7) << 2;                                          \
            cpa16(sA + ((stg) * STG_F + SW(row, kk)) * 4,                      \
                  &A[(size_t)(m0 + row) * CC + (kbase) + kk]);                 \
            cpa16(sB + ((stg) * STG_F + SW(row, kk)) * 4,                      \
                  &W[(size_t)(n0 + row) * CC + (kbase) + kk]);                 \
        }                                                                      \
    } while (0)

    STAGE_LOAD(0, 0);
    CP_COMMIT();

    int buf = 0;
    for (int k0 = 0; k0 < CC; k0 += BK2) {
        if (k0 + BK2 < CC) {
            STAGE_LOAD(buf ^ 1, k0 + BK2);
            CP_COMMIT();
            CP_WAIT(1);
        } else {
            CP_WAIT(0);
        }
        __syncthreads();

        const float* Ab = As + buf * STG_F;
        const float* Bb = Bs + buf * STG_F;
#pragma unroll
        for (int ks = 0; ks < BK2; ks += 8) {
            unsigned af[2][4];
#pragma unroll
            for (int mi = 0; mi < 2; mi++) {
                int rlo = wm + mi * 16 + lq;
                af[mi][0] = __float_as_uint(Ab[SW(rlo,     ks + lr)]);
                af[mi][1] = __float_as_uint(Ab[SW(rlo + 8, ks + lr)]);
                af[mi][2] = __float_as_uint(Ab[SW(rlo,     ks + 4 + lr)]);
                af[mi][3] = __float_as_uint(Ab[SW(rlo + 8, ks + 4 + lr)]);
            }
            unsigned bf[8][2];
#pragma unroll
            for (int ni = 0; ni < 8; ni++) {
                int col = wn + ni * 8 + lq;
                bf[ni][0] = __float_as_uint(Bb[SW(col, ks + lr)]);
                bf[ni][1] = __float_as_uint(Bb[SW(col, ks + 4 + lr)]);
            }
#pragma unroll
            for (int mi = 0; mi < 2; mi++)
#pragma unroll
                for (int ni = 0; ni < 8; ni++)
                    MMA_TF32(c[mi][ni], af[mi][0], af[mi][1], af[mi][2], af[mi][3],
                             bf[ni][0], bf[ni][1]);
        }
        __syncthreads();
        buf ^= 1;
    }

    if (do_rope) {
#pragma unroll
        for (int mi = 0; mi < 2; mi++) {
            int rbase = m0 + wm + mi * 16 + lq;
#pragma unroll
            for (int rr = 0; rr < 2; rr++) {
                int t = (rbase + 8 * rr) & (TT - 1);
#pragma unroll
                for (int ni = 0; ni < 4; ni++) {
#pragma unroll
                    for (int c2 = 0; c2 < 2; c2++) {
                        int j = ni * 8 + 2 * lr + c2;
                        float cs, sn;
                        safe_sincos((float)t * c_inv[j], &cs, &sn);
                        int idx = 2 * rr + c2;
                        float a1 = c[mi][ni][idx], a2 = c[mi][ni + 4][idx];
                        c[mi][ni][idx]     = a1 * cs - a2 * sn;
                        c[mi][ni + 4][idx] = a2 * cs + a1 * sn;
                    }
                }
            }
        }
    }

#pragma unroll
    for (int mi = 0; mi < 2; mi++) {
        int rlo = m0 + wm + mi * 16 + lq;
#pragma unroll
        for (int ni = 0; ni < 8; ni++) {
            int cc = n0 + wn + ni * 8 + 2 * lr;
            *(float2*)&Cout[(size_t)rlo * CC + cc] =
                make_float2(c[mi][ni][0], c[mi][ni][1]);
            *(float2*)&Cout[(size_t)(rlo + 8) * CC + cc] =
                make_float2(c[mi][ni][2], c[mi][ni][3]);
        }
    }
#undef STAGE_LOAD
}

// ---------------- flash attention: 128-row Q tile, 64-key tiles --------------
// 256 thr = 8 warps; warp w owns q-rows [w*16, w*16+16). K/V staged once per
// 128 q-rows (halves staging vs 64-row tiles). Warps skip fully-masked tiles.
#define QLD 68
#define VLD 72
#define FLASH_SMEM ((2 * 128 * QLD + 64 * QLD + 64 * VLD) * 4)   // 105472 B

__global__ __launch_bounds__(256)
void flash_tc()
{
    extern __shared__ unsigned fsm[];
    unsigned* Qs = fsm;                          // 128 x QLD
    unsigned* Ps = fsm + 128 * QLD;              // 128 x QLD (warp-private rows)
    unsigned* Ks = fsm + 2 * 128 * QLD;          // 64 x QLD
    unsigned* Vs = fsm + 2 * 128 * QLD + 64 * QLD; // 64 x VLD

    const int tid  = threadIdx.x;
    const int lane = tid & 31;
    const int strip = (tid >> 5) * 16;           // 0..112
    const int lq = lane >> 2, lr = lane & 3;

    const int bh = blockIdx.y;
    const int b = bh >> 4, h = bh & 15;
    const int qb = gridDim.x - 1 - blockIdx.x;   // 0..31, longest first
    const int t0q = qb * 128;
    const size_t base = (size_t)b * TT * CC + h * DD;

    // Q staged pre-scaled into log2 domain
    const float qsc = 0.125f * 1.44269504f;
#pragma unroll
    for (int it = 0; it < 8; it++) {
        int lin = tid + it * 256;                // 2048 float4 slots
        int row = lin >> 4, c4 = (lin & 15) << 2;
        float4 a = *(const float4*)&g_q2[base + (size_t)(t0q + row) * CC + c4];
        *(uint4*)&Qs[row * QLD + c4] =
            make_uint4(f2tf32(a.x * qsc), f2tf32(a.y * qsc),
                       f2tf32(a.z * qsc), f2tf32(a.w * qsc));
    }

    float m_i[2] = {-INFINITY, -INFINITY};
    float l_i[2] = {0.f, 0.f};
    float oa[8][4];
#pragma unroll
    for (int ni = 0; ni < 8; ni++)
#pragma unroll
        for (int r = 0; r < 4; r++) oa[ni][r] = 0.f;

    const int ntiles = 2 * (qb + 1);
    for (int jt = 0; jt < ntiles; jt++) {
        __syncthreads();                          // K/V reuse + Q visible (jt 0)
        const int t0k = jt * 64;
#pragma unroll
        for (int it = 0; it < 4; it++) {
            int lin = tid + it * 256;             // 1024 float4 slots
            int row = lin >> 4, c4 = (lin & 15) << 2;
            float4 kv = *(const float4*)&g_k2[base + (size_t)(t0k + row) * CC + c4];
            *(uint4*)&Ks[row * QLD + c4] =
                make_uint4(f2tf32(kv.x), f2tf32(kv.y), f2tf32(kv.z), f2tf32(kv.w));
            float4 vv = *(const float4*)&g_v[base + (size_t)(t0k + row) * CC + c4];
            *(uint4*)&Vs[row * VLD + c4] =
                make_uint4(f2tf32(vv.x), f2tf32(vv.y), f2tf32(vv.z), f2tf32(vv.w));
        }
        __syncthreads();

        // warp entirely above diagonal for this k-tile -> nothing to do
        if (t0k <= t0q + strip + 15) {
            float sa[8][4];
#pragma unroll
            for (int ni = 0; ni < 8; ni++)
#pragma unroll
                for (int r = 0; r < 4; r++) sa[ni][r] = 0.f;

#pragma unroll
            for (int ks = 0; ks < 64; ks += 8) {
                unsigned a0 = Qs[(strip + lq) * QLD + ks + lr];
                unsigned a1 = Qs[(strip + lq + 8) * QLD + ks + lr];
                unsigned a2 = Qs[(strip + lq) * QLD + ks + 4 + lr];
                unsigned a3 = Qs[(strip + lq + 8) * QLD + ks + 4 + lr];
#pragma unroll
                for (int ni = 0; ni < 8; ni++) {
                    unsigned b0 = Ks[(ni * 8 + lq) * QLD + ks + lr];
                    unsigned b1 = Ks[(ni * 8 + lq) * QLD + ks + 4 + lr];
                    MMA_TF32(sa[ni], a0, a1, a2, a3, b0, b1);
                }
            }

            // causal mask if this tile overlaps the warp's diagonal band
            if (t0k + 63 > t0q + strip) {
                int r0 = t0q + strip + lq, r1 = r0 + 8;
#pragma unroll
                for (int ni = 0; ni < 8; ni++) {
                    int colg = t0k + ni * 8 + 2 * lr;
                    if (colg     > r0) sa[ni][0] = -1e30f;
                    if (colg + 1 > r0) sa[ni][1] = -1e30f;
                    if (colg     > r1) sa[ni][2] = -1e30f;
                    if (colg + 1 > r1) sa[ni][3] = -1e30f;
                }
            }

            // online softmax (exp2 domain); quad lr holds the row
#pragma unroll
            for (int r = 0; r < 2; r++) {
                float mx = fmaxf(sa[0][2 * r], sa[0][2 * r + 1]);
#pragma unroll
                for (int ni = 1; ni < 8; ni++)
                    mx = fmaxf(mx, fmaxf(sa[ni][2 * r], sa[ni][2 * r + 1]));
                mx = fmaxf(mx, __shfl_xor_sync(0xffffffffu, mx, 1));
                mx = fmaxf(mx, __shfl_xor_sync(0xffffffffu, mx, 2));
                float mnew  = fmaxf(m_i[r], mx);
                float alpha = fexp2(m_i[r] - mnew);
                m_i[r] = mnew;
                float sum = 0.f;
                int prow = (strip + lq + 8 * r) * QLD;
#pragma unroll
                for (int ni = 0; ni < 8; ni++) {
                    float p0 = fexp2(sa[ni][2 * r] - mnew);
                    float p1 = fexp2(sa[ni][2 * r + 1] - mnew);
                    sum += p0 + p1;
                    Ps[prow + ni * 8 + 2 * lr]     = f2tf32(p0);
                    Ps[prow + ni * 8 + 2 * lr + 1] = f2tf32(p1);
                }
                sum += __shfl_xor_sync(0xffffffffu, sum, 1);
                sum += __shfl_xor_sync(0xffffffffu, sum, 2);
                l_i[r] = l_i[r] * alpha + sum;
#pragma unroll
                for (int ni = 0; ni < 8; ni++) {
                    oa[ni][2 * r]     *= alpha;
                    oa[ni][2 * r + 1] *= alpha;
                }
            }
            __syncwarp();                         // Ps rows are warp-private

            // O += Ps @ Vs
#pragma unroll
            for (int ks = 0; ks < 64; ks += 8) {
                unsigned a0 = Ps[(strip + lq) * QLD + ks + lr];
                unsigned a1 = Ps[(strip + lq + 8) * QLD + ks + lr];
                unsigned a2 = Ps[(strip + lq) * QLD + ks + 4 + lr];
                unsigned a3 = Ps[(strip + lq + 8) * QLD + ks + 4 + lr];
#pragma unroll
                for (int ni = 0; ni < 8; ni++) {
                    unsigned b0 = Vs[(ks + lr) * VLD + ni * 8 + lq];
                    unsigned b1 = Vs[(ks + 4 + lr) * VLD + ni * 8 + lq];
                    MMA_TF32(oa[ni], a0, a1, a2, a3, b0, b1);
                }
            }
        }
    }

    // epilogue: normalize + tf32-round
    float inv0 = 1.f / l_i[0], inv1 = 1.f / l_i[1];
    int t0 = t0q + strip + lq;
#pragma unroll
    for (int ni = 0; ni < 8; ni++) {
        int d = ni * 8 + 2 * lr;
        *(uint2*)&g_o[base + (size_t)t0 * CC + d] =
            make_uint2(f2tf32(oa[ni][0] * inv0), f2tf32(oa[ni][1] * inv0));
        *(uint2*)&g_o[base + (size_t)(t0 + 8) * CC + d] =
            make_uint2(f2tf32(oa[ni][2] * inv1), f2tf32(oa[ni][3] * inv1));
    }
}

// ---------------- launch -----------------------------------------------------
static float hA[1024], hB[1024], hC[1024], hD[1024], hV1[1024], ho1[1024];
static float hW[(size_t)CC * CC];
static float hx2[2 * CC];

extern "C" void kernel_launch(void* const* d_in, const int* in_sizes, int n_in,
                              void* d_out, int out_size)
{
    const float* x  = (const float*)d_in[0];
    const float* Wq = (const float*)d_in[1];
    const float* Wk = (const float*)d_in[2];
    const float* Wv = (const float*)d_in[3];
    const float* Wo = (const float*)d_in[4];

    float *xt, *wt, *q2, *k2, *vp, *op;
    cudaGetSymbolAddress((void**)&xt, g_xt);
    cudaGetSymbolAddress((void**)&wt, g_wt);
    cudaGetSymbolAddress((void**)&q2, g_q2);
    cudaGetSymbolAddress((void**)&k2, g_k2);
    cudaGetSymbolAddress((void**)&vp, g_v);
    cudaGetSymbolAddress((void**)&op, g_o);
    float* wt0 = wt;
    float* wt1 = wt + (size_t)CC * CC;
    float* wt2 = wt + 2 * (size_t)CC * CC;
    float* wt3 = wt + 3 * (size_t)CC * CC;

    static int smem_set = 0;
    if (!smem_set) {
        cudaFuncSetAttribute(flash_tc,
                             cudaFuncAttributeMaxDynamicSharedMemorySize,
                             FLASH_SMEM);
        cudaFuncSetAttribute(pgemm,
                             cudaFuncAttributeMaxDynamicSharedMemorySize,
                             GEMM_SMEM);
        smem_set = 1;
    }

    // pre-round to tf32 (RNA) once
    cvt_tf32<<<(MM * CC) / 1024, 256>>>(x, xt);
    cvt_tf32<<<(CC * CC) / 1024, 256>>>(Wq, wt0);
    cvt_tf32<<<(CC * CC) / 1024, 256>>>(Wk, wt1);
    cvt_tf32<<<(CC * CC) / 1024, 256>>>(Wv, wt2);
    cvt_tf32<<<(CC * CC) / 1024, 256>>>(Wo, wt3);

    dim3 gg(CC / GBN, MM / GBM);   // (8, 64)
    pgemm<<<gg, 256, GEMM_SMEM>>>(xt, wt0, q2, 1);   // Q + fused rope
    pgemm<<<gg, 256, GEMM_SMEM>>>(xt, wt1, k2, 1);   // K + fused rope
    pgemm<<<gg, 256, GEMM_SMEM>>>(xt, wt2, vp, 0);   // V

    flash_tc<<<dim3(TT / 128, BB * HH), 256, FLASH_SMEM>>>();

    pgemm<<<gg, 256, GEMM_SMEM>>>(op, wt3, (float*)d_out, 0);

    // ---- capture-guarded host verification; rc=3 only on failure ------------
    cudaStreamCaptureStatus csx = cudaStreamCaptureStatusNone;
    cudaStreamIsCapturing(0, &csx);
    if (csx != cudaStreamCaptureStatusNone) return;

    cudaError_t e = cudaDeviceSynchronize();
    if (e != cudaSuccess) {
        printf("[HC] pipeline error: %s\n", cudaGetErrorString(e));
        fflush(stdout); exit(3);
    }
    int bad = 0;

    // (1)+(2) q2 rows 0 and 1 vs host x.Wq^T (+rotation at t=1)
    cudaMemcpy(hW, Wq, (size_t)CC * CC * 4, cudaMemcpyDeviceToHost);
    cudaMemcpy(hx2, x, 2 * CC * 4, cudaMemcpyDeviceToHost);
    cudaMemcpyFromSymbol(hA, g_q2, 1024 * 4, 0);
    cudaMemcpyFromSymbol(hB, g_q2, 1024 * 4, (size_t)CC * 4);
    {
        static double raw1[1024];
        for (int ch = 0; ch < 1024; ch++) {
            double e0 = 0, e1 = 0;
            for (int k = 0; k < 1024; k++) {
                e0 += (double)hx2[k] * hW[(size_t)ch * CC + k];
                e1 += (double)hx2[CC + k] * hW[(size_t)ch * CC + k];
            }
            raw1[ch] = e1;
            if (fabs(e0 - hA[ch]) > 4e-3 * (fabs(e0) + 1.0) && bad < 8) {
                printf("[HC] q2 t0 ch=%d got %.6g exp %.6g\n", ch, hA[ch], e0);
                bad++;
            }
        }
        for (int h = 0; h < HH && bad < 8; h++)
            for (int j = 0; j < 32 && bad < 8; j++) {
                int ch = h * DD + j;
                double cq = cos((double)h_inv[j]), sq = sin((double)h_inv[j]);
                double r1 = raw1[ch] * cq - raw1[ch + 32] * sq;
                double r2 = raw1[ch + 32] * cq + raw1[ch] * sq;
                if (fabs(r1 - hB[ch]) > 4e-3 * (fabs(r1) + 1.0) ||
                    fabs(r2 - hB[ch + 32]) > 4e-3 * (fabs(r2) + 1.0)) {
                    printf("[HC] q2 t1 h=%d j=%d got(%.6g,%.6g) exp(%.6g,%.6g)\n",
                           h, j, hB[ch], hB[ch + 32], r1, r2);
                    bad++;
                }
            }
    }
    // (3) attention t=0: o == v
    cudaMemcpyFromSymbol(hC, g_o, 1024 * 4, 0);
    cudaMemcpyFromSymbol(hD, g_v, 1024 * 4, 0);
    for (int ch = 0; ch < 1024 && bad < 8; ch++)
        if (fabsf(hC[ch] - hD[ch]) > 2e-3f * (fabsf(hD[ch]) + 1e-1f)) {
            printf("[HC] attn t0 ch=%d o=%.6g v=%.6g\n", ch, hC[ch], hD[ch]);
            bad++;
        }
    // (4) attention t=1: two-key softmax vs host
    {
        cudaMemcpyFromSymbol(hA, g_q2, 1024 * 4, (size_t)CC * 4);
        cudaMemcpyFromSymbol(hB, g_k2, 1024 * 4, 0);
        cudaMemcpyFromSymbol(hC, g_k2, 1024 * 4, (size_t)CC * 4);
        cudaMemcpyFromSymbol(hD, g_v,  1024 * 4, 0);
        cudaMemcpyFromSymbol(hV1, g_v, 1024 * 4, (size_t)CC * 4);
        cudaMemcpyFromSymbol(ho1, g_o, 1024 * 4, (size_t)CC * 4);
        for (int h = 0; h < HH && bad < 8; h++) {
            double s0 = 0, s1 = 0;
            for (int d = 0; d < DD; d++) {
                s0 += (double)hA[h * DD + d] * hB[h * DD + d];
                s1 += (double)hA[h * DD + d] * hC[h * DD + d];
            }
            s0 *= 0.125; s1 *= 0.125;
            double m = s0 > s1 ? s0 : s1;
            double p0 = exp(s0 - m), p1 = exp(s1 - m), Z = p0 + p1;
            for (int d = 0; d < DD && bad < 8; d++) {
                double oe = (p0 * hD[h * DD + d] + p1 * hV1[h * DD + d]) / Z;
                if (fabs(oe - ho1[h * DD + d]) > 3e-3) {
                    printf("[HC] attn t1 h=%d d=%d got %.6g exp %.6g\n",
                           h, d, ho1[h * DD + d], oe);
                    bad++;
                }
            }
        }
    }
    // (5) final out[0,0:4] vs host dot
    {
        cudaMemcpyFromSymbol(hC, g_o, 1024 * 4, 0);
        cudaMemcpy(hW, Wo, 4096 * 4, cudaMemcpyDeviceToHost);
        float hout[4];
        cudaMemcpy(hout, d_out, 16, cudaMemcpyDeviceToHost);
        for (int r = 0; r < 4; r++) {
            double ex = 0;
            for (int k = 0; k < 1024; k++) ex += (double)hC[k] * hW[r * 1024 + k];
            if (fabs(ex - hout[r]) > 2e-3 * (fabs(ex) + 1.0)) {
                printf("[HC] out0 r=%d got %.6g exp %.6g\n", r, hout[r], ex);
                bad++;
            }
        }
    }
    if (bad) { printf("[HC] FAILED %d checks\n", bad); fflush(stdout); exit(3); }
}